// round 2
// baseline (speedup 1.0000x reference)
#include <cuda_runtime.h>
#include <cuda_bf16.h>

// GNNIntraAgg: out[b, :] = relu( (1/K) * sum_k features[neigh_ids[b,k], :] )
// B=16384, K=32, N=100000, D=256 (fp32).
//
// Strategy: L2-bandwidth-bound gather. Feature table (102.4 MB) fits in L2
// (~126 MB), so gather traffic (536 MB) is served from L2 after warmup.
// float4 loads, 4 rows per 256-thread block, ids staged in smem
// (broadcast reads), fully unrolled K loop for memory-level parallelism.

#define K_NEIGH 32
#define D_VEC 64              // D=256 floats = 64 float4
#define ROWS_PER_BLOCK 4
#define THREADS (ROWS_PER_BLOCK * D_VEC)   // 256

__global__ __launch_bounds__(THREADS, 8)
void gnn_agg_kernel(const int* __restrict__ neigh_ids,
                    const float4* __restrict__ feat,
                    float4* __restrict__ out,
                    int B)
{
    __shared__ int s_ids[ROWS_PER_BLOCK][K_NEIGH];

    const int tid = threadIdx.x;
    const int row0 = blockIdx.x * ROWS_PER_BLOCK;

    // Stage the 4 rows' neighbor ids (128 ints) into shared memory.
    if (tid < ROWS_PER_BLOCK * K_NEIGH) {
        const int r = tid >> 5;       // row within block
        const int k = tid & 31;       // neighbor index
        s_ids[r][k] = neigh_ids[(row0 + r) * K_NEIGH + k];
    }
    __syncthreads();

    const int r = tid >> 6;           // 0..3  : row within block
    const int c = tid & 63;           // 0..63 : float4 column

    float4 sum = make_float4(0.f, 0.f, 0.f, 0.f);

#pragma unroll
    for (int k = 0; k < K_NEIGH; ++k) {
        // All lanes in a warp read the same smem word -> broadcast, no conflict.
        const long id = s_ids[r][k];
        const float4 v = __ldg(&feat[id * D_VEC + c]);
        sum.x += v.x;
        sum.y += v.y;
        sum.z += v.z;
        sum.w += v.w;
    }

    const float inv = 1.0f / (float)K_NEIGH;
    float4 o;
    o.x = fmaxf(sum.x * inv, 0.0f);
    o.y = fmaxf(sum.y * inv, 0.0f);
    o.z = fmaxf(sum.z * inv, 0.0f);
    o.w = fmaxf(sum.w * inv, 0.0f);

    out[(long)(row0 + r) * D_VEC + c] = o;
}

extern "C" void kernel_launch(void* const* d_in, const int* in_sizes, int n_in,
                              void* d_out, int out_size)
{
    const int* neigh_ids  = (const int*)d_in[0];      // [B, K] int32
    const float4* feat    = (const float4*)d_in[1];   // [N, D] fp32 as [N, 64] float4
    float4* out           = (float4*)d_out;           // [B, D] fp32

    const int B = in_sizes[0] / K_NEIGH;              // 16384
    const int grid = B / ROWS_PER_BLOCK;              // 4096

    gnn_agg_kernel<<<grid, THREADS>>>(neigh_ids, feat, out, B);
}

// round 4
// speedup vs baseline: 1.2461x; 1.2461x over previous
#include <cuda_runtime.h>
#include <cuda_bf16.h>

// GNNIntraAgg: out[b, :] = relu( (1/K) * sum_k features[neigh_ids[b,k], :] )
// B=16384, K=32, N=100000, D=256 (fp32).
//
// R4: sm_103 requires 256-bit loads for L2::evict_last -> use ld.global.nc
// .L2::evict_last.v8.b32 (LDG.256). One warp per output row: 32 lanes x 32B
// = 1024B contiguous per neighbor row. 4-deep load batches for MLP.
// Output stores streaming (cs) so they don't evict the L2-resident table.

#define K_NEIGH 32
#define WARPS_PER_BLOCK 8
#define THREADS (WARPS_PER_BLOCK * 32)   // 256
#define LBATCH 4                          // outstanding 32B loads per thread

__device__ __forceinline__ void ldg256_evict_last(const float* p, float4& a, float4& b)
{
    asm volatile("ld.global.nc.L2::evict_last.v8.b32 "
                 "{%0,%1,%2,%3,%4,%5,%6,%7}, [%8];"
                 : "=f"(a.x), "=f"(a.y), "=f"(a.z), "=f"(a.w),
                   "=f"(b.x), "=f"(b.y), "=f"(b.z), "=f"(b.w)
                 : "l"(p));
}

__global__ __launch_bounds__(THREADS)
void gnn_agg_kernel(const int* __restrict__ neigh_ids,
                    const float* __restrict__ feat,
                    float4* __restrict__ out,
                    int B)
{
    __shared__ int s_ids[WARPS_PER_BLOCK][K_NEIGH];

    const int tid  = threadIdx.x;
    const int row0 = blockIdx.x * WARPS_PER_BLOCK;

    // Stage this block's 8 rows of neighbor ids (256 ints, one per thread).
    {
        const int r = tid >> 5;
        const int k = tid & 31;
        s_ids[r][k] = neigh_ids[(row0 + r) * K_NEIGH + k];
    }
    __syncthreads();

    const int w    = tid >> 5;        // warp = output row within block
    const int lane = tid & 31;        // lane = 8-float chunk (32B) of the row

    float acc[8];
#pragma unroll
    for (int i = 0; i < 8; ++i) acc[i] = 0.f;

#pragma unroll
    for (int kb = 0; kb < K_NEIGH; kb += LBATCH) {
        float4 va[LBATCH], vb[LBATCH];
#pragma unroll
        for (int j = 0; j < LBATCH; ++j) {
            const int id = s_ids[w][kb + j];             // warp-broadcast read
            const float* p = feat + (long)id * 256 + lane * 8;
            ldg256_evict_last(p, va[j], vb[j]);
        }
#pragma unroll
        for (int j = 0; j < LBATCH; ++j) {
            acc[0] += va[j].x;  acc[1] += va[j].y;
            acc[2] += va[j].z;  acc[3] += va[j].w;
            acc[4] += vb[j].x;  acc[5] += vb[j].y;
            acc[6] += vb[j].z;  acc[7] += vb[j].w;
        }
    }

    const float inv = 1.0f / (float)K_NEIGH;
    float4 o0, o1;
    o0.x = fmaxf(acc[0] * inv, 0.f);  o0.y = fmaxf(acc[1] * inv, 0.f);
    o0.z = fmaxf(acc[2] * inv, 0.f);  o0.w = fmaxf(acc[3] * inv, 0.f);
    o1.x = fmaxf(acc[4] * inv, 0.f);  o1.y = fmaxf(acc[5] * inv, 0.f);
    o1.z = fmaxf(acc[6] * inv, 0.f);  o1.w = fmaxf(acc[7] * inv, 0.f);

    // Streaming stores: don't evict the feature table from L2.
    float4* orow = out + (long)(row0 + w) * 64 + lane * 2;
    __stcs(orow,     o0);
    __stcs(orow + 1, o1);
}

extern "C" void kernel_launch(void* const* d_in, const int* in_sizes, int n_in,
                              void* d_out, int out_size)
{
    const int* neigh_ids = (const int*)d_in[0];     // [B, K] int32
    const float* feat    = (const float*)d_in[1];   // [N, D] fp32
    float4* out          = (float4*)d_out;          // [B, D] fp32

    const int B = in_sizes[0] / K_NEIGH;            // 16384
    const int grid = B / WARPS_PER_BLOCK;           // 2048

    gnn_agg_kernel<<<grid, THREADS>>>(neigh_ids, feat, out, B);
}